// round 6
// baseline (speedup 1.0000x reference)
#include <cuda_runtime.h>
#include <math.h>

#define NTHREADS 128
#define HID 64
#define GRID 296   // 2 CTAs/SM * 148 SMs

typedef unsigned long long u64;

// ---------------- SMEM layout (float offsets) ----------------
#define OFF_SW1 0
#define OFF_SB1 448
#define OFF_SW2 512
#define OFF_SB2 4608
#define OFF_SW3 4672
#define OFF_SB3 4736
#define OFF_AW1 4740
#define OFF_AB1 5188
#define OFF_AW2 5252
#define OFF_AB2 9348
#define OFF_AW3 9412
#define OFF_AB3 9476
#define OFF_FW1 9480
#define OFF_FB1 9864
#define OFF_FW2 9928
#define OFF_FB2 14024
#define OFF_FW3 14088
#define OFF_FB3 14152
#define OFF_RW1 14156
#define OFF_RB1 14476
#define OFF_RW2 14540
#define OFF_RB2 18636
#define OFF_RW3 18700
#define OFF_RB3 18892
#define OFF_IMEAN 18896
#define OFF_ISTD  18904
#define OFF_TMEAN 18912
#define OFF_TSTD  18916
#define SMEM_FLOATS 18920
#define SMEM_BYTES (SMEM_FLOATS * 4)

struct KParams {
    const float* in[30];
    float* out;
    int B;
};

__device__ __constant__ int kCnt[28] = {
    5, 5, 3, 3,
    448, 64, 4096, 64, 64, 1,
    448, 64, 4096, 64, 64, 1,
    384, 64, 4096, 64, 64, 1,
    320, 64, 4096, 64, 192, 3
};
__device__ __constant__ int kOff[28] = {
    OFF_IMEAN, OFF_ISTD, OFF_TMEAN, OFF_TSTD,
    OFF_SW1, OFF_SB1, OFF_SW2, OFF_SB2, OFF_SW3, OFF_SB3,
    OFF_AW1, OFF_AB1, OFF_AW2, OFF_AB2, OFF_AW3, OFF_AB3,
    OFF_FW1, OFF_FB1, OFF_FW2, OFF_FB2, OFF_FW3, OFF_FB3,
    OFF_RW1, OFF_RB1, OFF_RW2, OFF_RB2, OFF_RW3, OFF_RB3
};

// ---------------- packed f32x2 helpers ----------------
__device__ __forceinline__ u64 dup2(float a) {
    u64 r; asm("mov.b64 %0, {%1, %1};" : "=l"(r) : "f"(a)); return r;
}
__device__ __forceinline__ u64 pack2(float lo, float hi) {
    u64 r; asm("mov.b64 %0, {%1, %2};" : "=l"(r) : "f"(lo), "f"(hi)); return r;
}
__device__ __forceinline__ u64 ffma2(u64 a, u64 b, u64 c) {
    u64 d; asm("fma.rn.f32x2 %0, %1, %2, %3;" : "=l"(d) : "l"(a), "l"(b), "l"(c)); return d;
}
__device__ __forceinline__ float2 unpk2(u64 a) {
    float2 f; asm("mov.b64 {%0, %1}, %2;" : "=f"(f.x), "=f"(f.y) : "l"(a)); return f;
}

// accurate fast tanh: abs error ~1e-7, 2 MUFU (EX2 + RCP)
__device__ __forceinline__ float fast_tanhf(float x) {
    float ax = fabsf(x);
    float e  = __expf(2.0f * ax);
    float t  = 1.0f - __fdividef(2.0f, e + 1.0f);
    return (x < 0.0f) ? -t : t;
}

__device__ __forceinline__ float softplusf(float x) {
    float t = __expf(-fabsf(x));
    return fmaxf(x, 0.0f) + __logf(1.0f + t);
}

// Two rows through one MLP: DIN -> 64 (tanh) -> 64 (tanh) -> DOUT.
// Layer-1 computed in two 32-wide halves; tanh results are packed IN PLACE
// into the layer-1 accumulators (acc1 storage becomes h storage), then each
// half is consumed immediately by a partial layer-2 accumulation.
// Every weight LDS feeds 4 FFMA2 (2 rows).
template <int DIN, int DOUT>
__device__ __forceinline__ void run_mlp2(
    const float* __restrict__ xa, const float* __restrict__ xb,
    const float* __restrict__ sm,
    int oW1, int ob1, int oW2, int ob2, int oW3, int ob3,
    float* __restrict__ outa, float* __restrict__ outb)
{
    u64 acc2a[32], acc2b[32];
    {
        const ulonglong2* b2 = (const ulonglong2*)(sm + ob2);
#pragma unroll
        for (int j = 0; j < 16; j++) {
            ulonglong2 b = b2[j];
            acc2a[2*j] = b.x; acc2a[2*j+1] = b.y;
            acc2b[2*j] = b.x; acc2b[2*j+1] = b.y;
        }
    }

#pragma unroll
    for (int half = 0; half < 2; half++) {
        // ---- layer 1, output cols [half*32, half*32+32) ----
        u64 acc1a[16], acc1b[16];
        {
            const ulonglong2* b1 = (const ulonglong2*)(sm + ob1 + half * 32);
#pragma unroll
            for (int j = 0; j < 8; j++) {
                ulonglong2 b = b1[j];
                acc1a[2*j] = b.x; acc1a[2*j+1] = b.y;
                acc1b[2*j] = b.x; acc1b[2*j+1] = b.y;
            }
        }
#pragma unroll
        for (int i = 0; i < DIN; i++) {
            const ulonglong2* w = (const ulonglong2*)(sm + oW1 + i * HID + half * 32);
            u64 x2a = dup2(xa[i]);
            u64 x2b = dup2(xb[i]);
#pragma unroll
            for (int j = 0; j < 8; j++) {
                ulonglong2 wv = w[j];
                acc1a[2*j]   = ffma2(x2a, wv.x, acc1a[2*j]);
                acc1a[2*j+1] = ffma2(x2a, wv.y, acc1a[2*j+1]);
                acc1b[2*j]   = ffma2(x2b, wv.x, acc1b[2*j]);
                acc1b[2*j+1] = ffma2(x2b, wv.y, acc1b[2*j+1]);
            }
        }
        // tanh IN PLACE: acc1 registers become packed h
#pragma unroll
        for (int j = 0; j < 16; j++) {
            float2 va = unpk2(acc1a[j]);
            acc1a[j] = pack2(fast_tanhf(va.x), fast_tanhf(va.y));
            float2 vb = unpk2(acc1b[j]);
            acc1b[j] = pack2(fast_tanhf(vb.x), fast_tanhf(vb.y));
        }
        // ---- layer 2 partial: reduction rows i = half*32 + (2*jj+s) ----
#pragma unroll
        for (int jj = 0; jj < 16; jj++) {
            float2 va = unpk2(acc1a[jj]);
            float2 vb = unpk2(acc1b[jj]);
#pragma unroll
            for (int s = 0; s < 2; s++) {
                const ulonglong2* w =
                    (const ulonglong2*)(sm + oW2 + (half * 32 + 2*jj + s) * HID);
                u64 h2a = dup2(s ? va.y : va.x);
                u64 h2b = dup2(s ? vb.y : vb.x);
#pragma unroll
                for (int j = 0; j < 16; j++) {
                    ulonglong2 wv = w[j];
                    acc2a[2*j]   = ffma2(h2a, wv.x, acc2a[2*j]);
                    acc2a[2*j+1] = ffma2(h2a, wv.y, acc2a[2*j+1]);
                    acc2b[2*j]   = ffma2(h2b, wv.x, acc2b[2*j]);
                    acc2b[2*j+1] = ffma2(h2b, wv.y, acc2b[2*j+1]);
                }
            }
        }
    }

    // ---- layer 3: tanh(acc2) -> DOUT, streaming ----
    float oa[DOUT], ob_[DOUT];
#pragma unroll
    for (int o = 0; o < DOUT; o++) { float b = sm[ob3 + o]; oa[o] = b; ob_[o] = b; }
#pragma unroll
    for (int j = 0; j < 32; j++) {
        float2 va = unpk2(acc2a[j]);
        float ta0 = fast_tanhf(va.x), ta1 = fast_tanhf(va.y);
        float2 vb = unpk2(acc2b[j]);
        float tb0 = fast_tanhf(vb.x), tb1 = fast_tanhf(vb.y);
#pragma unroll
        for (int o = 0; o < DOUT; o++) {
            float w0 = sm[oW3 + (2*j)   * DOUT + o];
            float w1 = sm[oW3 + (2*j+1) * DOUT + o];
            oa[o]  = fmaf(ta0, w0, fmaf(ta1, w1, oa[o]));
            ob_[o] = fmaf(tb0, w0, fmaf(tb1, w1, ob_[o]));
        }
    }
#pragma unroll
    for (int o = 0; o < DOUT; o++) { outa[o] = oa[o]; outb[o] = ob_[o]; }
}

extern __shared__ float sm[];

__global__ void __launch_bounds__(NTHREADS, 2)
fused_mlp_kernel(KParams p)
{
    const int tid = threadIdx.x;

    // Stage all weights + norm params into SMEM once per CTA.
    for (int a = 0; a < 28; a++) {
        const float* src = p.in[a + 2];
        const int n = kCnt[a];
        const int o = kOff[a];
        for (int k = tid; k < n; k += NTHREADS) sm[o + k] = src[k];
    }
    __syncthreads();

    const float* xd0 = p.in[0];
    const float* utr = p.in[1];
    const int Btot = p.B;
    const int npairs = (Btot + 1) >> 1;
    const int stride = gridDim.x * NTHREADS;

    const float im0 = sm[OFF_IMEAN+0], im1 = sm[OFF_IMEAN+1], im2 = sm[OFF_IMEAN+2];
    const float im3 = sm[OFF_IMEAN+3], im4 = sm[OFF_IMEAN+4];
    const float is0 = sm[OFF_ISTD+0],  is1 = sm[OFF_ISTD+1],  is2 = sm[OFF_ISTD+2];
    const float is3 = sm[OFF_ISTD+3],  is4 = sm[OFF_ISTD+4];

    for (int pr = blockIdx.x * NTHREADS + tid; pr < npairs; pr += stride) {
        int ra = 2 * pr;
        int rb = 2 * pr + 1;
        bool hasb = (rb < Btot);
        int rbe = hasb ? rb : ra;

        float fa[5], fb[5]; // vx, vy, w, vel, delta per row
        {
            float a0 = xd0[ra*3+0], a1 = xd0[ra*3+1], a2 = xd0[ra*3+2];
            float a3 = utr[ra*2+0], a4 = utr[ra*2+1];
            fa[0] = __fdividef(a0 - im0, is0);
            fa[1] = __fdividef(a1 - im1, is1);
            fa[2] = __fdividef(a2 - im2, is2);
            fa[3] = __fdividef(a3 - im3, is3);
            fa[4] = __fdividef(a4 - im4, is4);
            float b0 = xd0[rbe*3+0], b1 = xd0[rbe*3+1], b2 = xd0[rbe*3+2];
            float b3 = utr[rbe*2+0], b4 = utr[rbe*2+1];
            fb[0] = __fdividef(b0 - im0, is0);
            fb[1] = __fdividef(b1 - im1, is1);
            fb[2] = __fdividef(b2 - im2, is2);
            fb[3] = __fdividef(b3 - im3, is3);
            fb[4] = __fdividef(b4 - im4, is4);
        }
        float vma = sqrtf(fmaf(fa[0], fa[0], fmaf(fa[1], fa[1], 1e-8f)));
        float vmb = sqrtf(fmaf(fb[0], fb[0], fmaf(fb[1], fb[1], 1e-8f)));
        float sga = (fa[0] > 0.0f) ? 1.0f : ((fa[0] < 0.0f) ? -1.0f : 0.0f);
        float sgb = (fb[0] > 0.0f) ? 1.0f : ((fb[0] < 0.0f) ? -1.0f : 0.0f);

        // steer MLP: [delta, vel, vx, vy, w, mag, sign]
        float sia[7] = {fa[4], fa[3], fa[0], fa[1], fa[2], vma, sga};
        float sib[7] = {fb[4], fb[3], fb[0], fb[1], fb[2], vmb, sgb};
        float soa, sob;
        run_mlp2<7,1>(sia, sib, sm, OFF_SW1, OFF_SB1, OFF_SW2, OFF_SB2, OFF_SW3, OFF_SB3, &soa, &sob);
        float dsa = 0.5f * fast_tanhf(soa);
        float dsb = 0.5f * fast_tanhf(sob);

        // acc MLP: [vel, delta, vx, mag, sign, vy, w]
        float aia[7] = {fa[3], fa[4], fa[0], vma, sga, fa[1], fa[2]};
        float aib[7] = {fb[3], fb[4], fb[0], vmb, sgb, fb[1], fb[2]};
        float aoa, aob;
        run_mlp2<7,1>(aia, aib, sm, OFF_AW1, OFF_AB1, OFF_AW2, OFF_AB2, OFF_AW3, OFF_AB3, &aoa, &aob);
        float daa = 0.5f * fast_tanhf(aoa);
        float dab = 0.5f * fast_tanhf(aob);

        float ue0a = fa[3] + daa, ue1a = fa[4] + dsa;
        float ue0b = fb[3] + dab, ue1b = fb[4] + dsb;

        // friction MLP: [vx, vy, w, ue0, ue1, DT]
        float fia[6] = {fa[0], fa[1], fa[2], ue0a, ue1a, 0.02f};
        float fib[6] = {fb[0], fb[1], fb[2], ue0b, ue1b, 0.02f};
        float foa, fob;
        run_mlp2<6,1>(fia, fib, sm, OFF_FW1, OFF_FB1, OFF_FW2, OFF_FB2, OFF_FW3, OFF_FB3, &foa, &fob);
        float fka = 1.0f + softplusf(foa);
        float fkb = 1.0f + softplusf(fob);

        // residual MLP: [vx, vy, w, ue0, ue1]
        float ria[5] = {fa[0], fa[1], fa[2], ue0a, ue1a};
        float rib[5] = {fb[0], fb[1], fb[2], ue0b, ue1b};
        float roa[3], rob[3];
        run_mlp2<5,3>(ria, rib, sm, OFF_RW1, OFF_RB1, OFF_RW2, OFF_RB2, OFF_RW3, OFF_RB3, roa, rob);

        float ts0 = sm[OFF_TSTD+0], ts1 = sm[OFF_TSTD+1], ts2 = sm[OFF_TSTD+2];
        float tm0 = sm[OFF_TMEAN+0], tm1 = sm[OFF_TMEAN+1], tm2 = sm[OFF_TMEAN+2];

        // outputs: [ut_eff_raw (B,2)] [friction_k (B,1)] [residual (B,3)]
        p.out[ra*2+0] = fmaf(ue0a, is3, im3);
        p.out[ra*2+1] = fmaf(ue1a, is4, im4);
        p.out[2*Btot + ra] = fka;
        p.out[3*Btot + ra*3 + 0] = fmaf(roa[0], ts0, tm0);
        p.out[3*Btot + ra*3 + 1] = fmaf(roa[1], ts1, tm1);
        p.out[3*Btot + ra*3 + 2] = fmaf(roa[2], ts2, tm2);
        if (hasb) {
            p.out[rb*2+0] = fmaf(ue0b, is3, im3);
            p.out[rb*2+1] = fmaf(ue1b, is4, im4);
            p.out[2*Btot + rb] = fkb;
            p.out[3*Btot + rb*3 + 0] = fmaf(rob[0], ts0, tm0);
            p.out[3*Btot + rb*3 + 1] = fmaf(rob[1], ts1, tm1);
            p.out[3*Btot + rb*3 + 2] = fmaf(rob[2], ts2, tm2);
        }
    }
}

extern "C" void kernel_launch(void* const* d_in, const int* in_sizes, int n_in,
                              void* d_out, int out_size)
{
    KParams p;
    for (int i = 0; i < 30; i++) p.in[i] = (const float*)d_in[i];
    p.out = (float*)d_out;
    p.B = in_sizes[0] / 3;

    cudaFuncSetAttribute(fused_mlp_kernel,
                         cudaFuncAttributeMaxDynamicSharedMemorySize, SMEM_BYTES);
    fused_mlp_kernel<<<GRID, NTHREADS, SMEM_BYTES>>>(p);
}

// round 7
// speedup vs baseline: 1.1452x; 1.1452x over previous
#include <cuda_runtime.h>
#include <math.h>

#define NTHREADS 256
#define HID 64
#define GRID 148   // 1 CTA per SM, persistent

typedef unsigned long long u64;

// ---------------- SMEM layout (float offsets) ----------------
#define OFF_SW1 0
#define OFF_SB1 448
#define OFF_SW2 512
#define OFF_SB2 4608
#define OFF_SW3 4672
#define OFF_SB3 4736
#define OFF_AW1 4740
#define OFF_AB1 5188
#define OFF_AW2 5252
#define OFF_AB2 9348
#define OFF_AW3 9412
#define OFF_AB3 9476
#define OFF_FW1 9480
#define OFF_FB1 9864
#define OFF_FW2 9928
#define OFF_FB2 14024
#define OFF_FW3 14088
#define OFF_FB3 14152
#define OFF_RW1 14156
#define OFF_RB1 14476
#define OFF_RW2 14540
#define OFF_RB2 18636
#define OFF_RW3 18700
#define OFF_RB3 18892
#define OFF_IMEAN 18896
#define OFF_ISTD  18904
#define OFF_TMEAN 18912
#define OFF_TSTD  18916
#define OFF_ACT   18920                    // float2 per (neuron, thread): rows a,b
#define ACT_FLOATS (NTHREADS * HID * 2)    // 32768 floats = 128 KB
#define SMEM_FLOATS (OFF_ACT + ACT_FLOATS)
#define SMEM_BYTES (SMEM_FLOATS * 4)       // ~206.8 KB

struct KParams {
    const float* in[30];
    float* out;
    int B;
};

__device__ __constant__ int kCnt[28] = {
    5, 5, 3, 3,
    448, 64, 4096, 64, 64, 1,
    448, 64, 4096, 64, 64, 1,
    384, 64, 4096, 64, 64, 1,
    320, 64, 4096, 64, 192, 3
};
__device__ __constant__ int kOff[28] = {
    OFF_IMEAN, OFF_ISTD, OFF_TMEAN, OFF_TSTD,
    OFF_SW1, OFF_SB1, OFF_SW2, OFF_SB2, OFF_SW3, OFF_SB3,
    OFF_AW1, OFF_AB1, OFF_AW2, OFF_AB2, OFF_AW3, OFF_AB3,
    OFF_FW1, OFF_FB1, OFF_FW2, OFF_FB2, OFF_FW3, OFF_FB3,
    OFF_RW1, OFF_RB1, OFF_RW2, OFF_RB2, OFF_RW3, OFF_RB3
};

// ---------------- packed f32x2 helpers ----------------
__device__ __forceinline__ u64 dup2(float a) {
    u64 r; asm("mov.b64 %0, {%1, %1};" : "=l"(r) : "f"(a)); return r;
}
__device__ __forceinline__ u64 ffma2(u64 a, u64 b, u64 c) {
    u64 d; asm("fma.rn.f32x2 %0, %1, %2, %3;" : "=l"(d) : "l"(a), "l"(b), "l"(c)); return d;
}
__device__ __forceinline__ float2 unpk2(u64 a) {
    float2 f; asm("mov.b64 {%0, %1}, %2;" : "=f"(f.x), "=f"(f.y) : "l"(a)); return f;
}

// accurate fast tanh: abs error ~1e-7, 2 MUFU (EX2 + RCP)
__device__ __forceinline__ float fast_tanhf(float x) {
    float ax = fabsf(x);
    float e  = __expf(2.0f * ax);
    float t  = 1.0f - __fdividef(2.0f, e + 1.0f);
    return (x < 0.0f) ? -t : t;
}

__device__ __forceinline__ float softplusf(float x) {
    float t = __expf(-fabsf(x));
    return fmaxf(x, 0.0f) + __logf(1.0f + t);
}

// Two rows through one MLP: DIN -> 64 (tanh) -> 64 (tanh) -> DOUT.
// Layer-1 in 32-output halves (acc1 = 32 regs); tanh(h1) goes to per-thread
// SMEM slots as float2(rowA,rowB). Layer-2 holds only acc2 (128 regs) and
// re-reads h via LDS.64. Every weight LDS feeds both rows.
template <int DIN, int DOUT>
__device__ __forceinline__ void run_mlp2(
    const float* __restrict__ xa, const float* __restrict__ xb,
    const float* __restrict__ sm,
    float2* __restrict__ act,   // already offset by tid; stride NTHREADS
    int oW1, int ob1, int oW2, int ob2, int oW3, int ob3,
    float* __restrict__ outa, float* __restrict__ outb)
{
    // ---- layer 1: DIN -> 64 in two 32-output halves ----
#pragma unroll
    for (int half = 0; half < 2; half++) {
        u64 acc1a[16], acc1b[16];
        {
            const ulonglong2* b1 = (const ulonglong2*)(sm + ob1 + half * 32);
#pragma unroll
            for (int j = 0; j < 8; j++) {
                ulonglong2 b = b1[j];
                acc1a[2*j] = b.x; acc1a[2*j+1] = b.y;
                acc1b[2*j] = b.x; acc1b[2*j+1] = b.y;
            }
        }
#pragma unroll
        for (int i = 0; i < DIN; i++) {
            const ulonglong2* w = (const ulonglong2*)(sm + oW1 + i * HID + half * 32);
            u64 x2a = dup2(xa[i]);
            u64 x2b = dup2(xb[i]);
#pragma unroll
            for (int j = 0; j < 8; j++) {
                ulonglong2 wv = w[j];
                acc1a[2*j]   = ffma2(x2a, wv.x, acc1a[2*j]);
                acc1a[2*j+1] = ffma2(x2a, wv.y, acc1a[2*j+1]);
                acc1b[2*j]   = ffma2(x2b, wv.x, acc1b[2*j]);
                acc1b[2*j+1] = ffma2(x2b, wv.y, acc1b[2*j+1]);
            }
        }
        // tanh -> smem as float2(rowA, rowB), neuron-major (conflict-free)
#pragma unroll
        for (int j = 0; j < 16; j++) {
            float2 va = unpk2(acc1a[j]);
            float2 vb = unpk2(acc1b[j]);
            act[(half * 32 + 2*j)     * NTHREADS] = make_float2(fast_tanhf(va.x), fast_tanhf(vb.x));
            act[(half * 32 + 2*j + 1) * NTHREADS] = make_float2(fast_tanhf(va.y), fast_tanhf(vb.y));
        }
    }

    // ---- layer 2: 64 -> 64 full width, acc2 = 128 regs ----
    u64 acc2a[32], acc2b[32];
    {
        const ulonglong2* b2 = (const ulonglong2*)(sm + ob2);
#pragma unroll
        for (int j = 0; j < 16; j++) {
            ulonglong2 b = b2[j];
            acc2a[2*j] = b.x; acc2a[2*j+1] = b.y;
            acc2b[2*j] = b.x; acc2b[2*j+1] = b.y;
        }
    }
#pragma unroll 4
    for (int i = 0; i < HID; i++) {
        float2 h = act[i * NTHREADS];   // per-thread LDS.64
        u64 h2a = dup2(h.x);
        u64 h2b = dup2(h.y);
        const ulonglong2* w = (const ulonglong2*)(sm + oW2 + i * HID);
#pragma unroll
        for (int j = 0; j < 16; j++) {
            ulonglong2 wv = w[j];
            acc2a[2*j]   = ffma2(h2a, wv.x, acc2a[2*j]);
            acc2a[2*j+1] = ffma2(h2a, wv.y, acc2a[2*j+1]);
            acc2b[2*j]   = ffma2(h2b, wv.x, acc2b[2*j]);
            acc2b[2*j+1] = ffma2(h2b, wv.y, acc2b[2*j+1]);
        }
    }

    // ---- layer 3: tanh(acc2) -> DOUT, streaming ----
    float oa[DOUT], ob_[DOUT];
#pragma unroll
    for (int o = 0; o < DOUT; o++) { float b = sm[ob3 + o]; oa[o] = b; ob_[o] = b; }
#pragma unroll
    for (int j = 0; j < 32; j++) {
        float2 va = unpk2(acc2a[j]);
        float ta0 = fast_tanhf(va.x), ta1 = fast_tanhf(va.y);
        float2 vb = unpk2(acc2b[j]);
        float tb0 = fast_tanhf(vb.x), tb1 = fast_tanhf(vb.y);
#pragma unroll
        for (int o = 0; o < DOUT; o++) {
            float w0 = sm[oW3 + (2*j)   * DOUT + o];
            float w1 = sm[oW3 + (2*j+1) * DOUT + o];
            oa[o]  = fmaf(ta0, w0, fmaf(ta1, w1, oa[o]));
            ob_[o] = fmaf(tb0, w0, fmaf(tb1, w1, ob_[o]));
        }
    }
#pragma unroll
    for (int o = 0; o < DOUT; o++) { outa[o] = oa[o]; outb[o] = ob_[o]; }
}

extern __shared__ float sm[];

__global__ void __launch_bounds__(NTHREADS, 1)
fused_mlp_kernel(KParams p)
{
    const int tid = threadIdx.x;

    // Stage all weights + norm params into SMEM once per CTA.
    for (int a = 0; a < 28; a++) {
        const float* src = p.in[a + 2];
        const int n = kCnt[a];
        const int o = kOff[a];
        for (int k = tid; k < n; k += NTHREADS) sm[o + k] = src[k];
    }
    __syncthreads();

    float2* act = (float2*)(sm + OFF_ACT) + tid;

    const float* xd0 = p.in[0];
    const float* utr = p.in[1];
    const int Btot = p.B;
    const int npairs = (Btot + 1) >> 1;
    const int stride = gridDim.x * NTHREADS;

    const float im0 = sm[OFF_IMEAN+0], im1 = sm[OFF_IMEAN+1], im2 = sm[OFF_IMEAN+2];
    const float im3 = sm[OFF_IMEAN+3], im4 = sm[OFF_IMEAN+4];
    const float is0 = sm[OFF_ISTD+0],  is1 = sm[OFF_ISTD+1],  is2 = sm[OFF_ISTD+2];
    const float is3 = sm[OFF_ISTD+3],  is4 = sm[OFF_ISTD+4];

    for (int pr = blockIdx.x * NTHREADS + tid; pr < npairs; pr += stride) {
        int ra = 2 * pr;
        int rb = 2 * pr + 1;
        bool hasb = (rb < Btot);
        int rbe = hasb ? rb : ra;

        float fa[5], fb[5]; // vx, vy, w, vel, delta per row
        {
            float a0 = xd0[ra*3+0], a1 = xd0[ra*3+1], a2 = xd0[ra*3+2];
            float a3 = utr[ra*2+0], a4 = utr[ra*2+1];
            fa[0] = __fdividef(a0 - im0, is0);
            fa[1] = __fdividef(a1 - im1, is1);
            fa[2] = __fdividef(a2 - im2, is2);
            fa[3] = __fdividef(a3 - im3, is3);
            fa[4] = __fdividef(a4 - im4, is4);
            float b0 = xd0[rbe*3+0], b1 = xd0[rbe*3+1], b2 = xd0[rbe*3+2];
            float b3 = utr[rbe*2+0], b4 = utr[rbe*2+1];
            fb[0] = __fdividef(b0 - im0, is0);
            fb[1] = __fdividef(b1 - im1, is1);
            fb[2] = __fdividef(b2 - im2, is2);
            fb[3] = __fdividef(b3 - im3, is3);
            fb[4] = __fdividef(b4 - im4, is4);
        }
        float vma = sqrtf(fmaf(fa[0], fa[0], fmaf(fa[1], fa[1], 1e-8f)));
        float vmb = sqrtf(fmaf(fb[0], fb[0], fmaf(fb[1], fb[1], 1e-8f)));
        float sga = (fa[0] > 0.0f) ? 1.0f : ((fa[0] < 0.0f) ? -1.0f : 0.0f);
        float sgb = (fb[0] > 0.0f) ? 1.0f : ((fb[0] < 0.0f) ? -1.0f : 0.0f);

        // steer MLP: [delta, vel, vx, vy, w, mag, sign]
        float sia[7] = {fa[4], fa[3], fa[0], fa[1], fa[2], vma, sga};
        float sib[7] = {fb[4], fb[3], fb[0], fb[1], fb[2], vmb, sgb};
        float soa, sob;
        run_mlp2<7,1>(sia, sib, sm, act, OFF_SW1, OFF_SB1, OFF_SW2, OFF_SB2, OFF_SW3, OFF_SB3, &soa, &sob);
        float dsa = 0.5f * fast_tanhf(soa);
        float dsb = 0.5f * fast_tanhf(sob);

        // acc MLP: [vel, delta, vx, mag, sign, vy, w]
        float aia[7] = {fa[3], fa[4], fa[0], vma, sga, fa[1], fa[2]};
        float aib[7] = {fb[3], fb[4], fb[0], vmb, sgb, fb[1], fb[2]};
        float aoa, aob;
        run_mlp2<7,1>(aia, aib, sm, act, OFF_AW1, OFF_AB1, OFF_AW2, OFF_AB2, OFF_AW3, OFF_AB3, &aoa, &aob);
        float daa = 0.5f * fast_tanhf(aoa);
        float dab = 0.5f * fast_tanhf(aob);

        float ue0a = fa[3] + daa, ue1a = fa[4] + dsa;
        float ue0b = fb[3] + dab, ue1b = fb[4] + dsb;

        // friction MLP: [vx, vy, w, ue0, ue1, DT]
        float fia[6] = {fa[0], fa[1], fa[2], ue0a, ue1a, 0.02f};
        float fib[6] = {fb[0], fb[1], fb[2], ue0b, ue1b, 0.02f};
        float foa, fob;
        run_mlp2<6,1>(fia, fib, sm, act, OFF_FW1, OFF_FB1, OFF_FW2, OFF_FB2, OFF_FW3, OFF_FB3, &foa, &fob);
        float fka = 1.0f + softplusf(foa);
        float fkb = 1.0f + softplusf(fob);

        // residual MLP: [vx, vy, w, ue0, ue1]
        float ria[5] = {fa[0], fa[1], fa[2], ue0a, ue1a};
        float rib[5] = {fb[0], fb[1], fb[2], ue0b, ue1b};
        float roa[3], rob[3];
        run_mlp2<5,3>(ria, rib, sm, act, OFF_RW1, OFF_RB1, OFF_RW2, OFF_RB2, OFF_RW3, OFF_RB3, roa, rob);

        float ts0 = sm[OFF_TSTD+0], ts1 = sm[OFF_TSTD+1], ts2 = sm[OFF_TSTD+2];
        float tm0 = sm[OFF_TMEAN+0], tm1 = sm[OFF_TMEAN+1], tm2 = sm[OFF_TMEAN+2];

        // outputs: [ut_eff_raw (B,2)] [friction_k (B,1)] [residual (B,3)]
        p.out[ra*2+0] = fmaf(ue0a, is3, im3);
        p.out[ra*2+1] = fmaf(ue1a, is4, im4);
        p.out[2*Btot + ra] = fka;
        p.out[3*Btot + ra*3 + 0] = fmaf(roa[0], ts0, tm0);
        p.out[3*Btot + ra*3 + 1] = fmaf(roa[1], ts1, tm1);
        p.out[3*Btot + ra*3 + 2] = fmaf(roa[2], ts2, tm2);
        if (hasb) {
            p.out[rb*2+0] = fmaf(ue0b, is3, im3);
            p.out[rb*2+1] = fmaf(ue1b, is4, im4);
            p.out[2*Btot + rb] = fkb;
            p.out[3*Btot + rb*3 + 0] = fmaf(rob[0], ts0, tm0);
            p.out[3*Btot + rb*3 + 1] = fmaf(rob[1], ts1, tm1);
            p.out[3*Btot + rb*3 + 2] = fmaf(rob[2], ts2, tm2);
        }
    }
}

extern "C" void kernel_launch(void* const* d_in, const int* in_sizes, int n_in,
                              void* d_out, int out_size)
{
    KParams p;
    for (int i = 0; i < 30; i++) p.in[i] = (const float*)d_in[i];
    p.out = (float*)d_out;
    p.B = in_sizes[0] / 3;

    cudaFuncSetAttribute(fused_mlp_kernel,
                         cudaFuncAttributeMaxDynamicSharedMemorySize, SMEM_BYTES);
    fused_mlp_kernel<<<GRID, NTHREADS, SMEM_BYTES>>>(p);
}

// round 8
// speedup vs baseline: 1.1755x; 1.0265x over previous
#include <cuda_runtime.h>
#include <math.h>

#define NTHREADS 256
#define HID 64
#define GRID 148   // 1 CTA per SM, persistent

typedef unsigned long long u64;

// ---------------- SMEM layout (float offsets) ----------------
#define OFF_SW1 0
#define OFF_SB1 448
#define OFF_SW2 512
#define OFF_SB2 4608
#define OFF_SW3 4672
#define OFF_SB3 4736
#define OFF_AW1 4740
#define OFF_AB1 5188
#define OFF_AW2 5252
#define OFF_AB2 9348
#define OFF_AW3 9412
#define OFF_AB3 9476
#define OFF_FW1 9480
#define OFF_FB1 9864
#define OFF_FW2 9928
#define OFF_FB2 14024
#define OFF_FW3 14088
#define OFF_FB3 14152
#define OFF_RW1 14156
#define OFF_RB1 14476
#define OFF_RW2 14540
#define OFF_RB2 18636
#define OFF_RW3 18700
#define OFF_RB3 18892
#define OFF_IMEAN 18896
#define OFF_ISTD  18904
#define OFF_TMEAN 18912
#define OFF_TSTD  18916
#define OFF_ACT   18920                    // float2 per (neuron, thread): rows a,b
#define ACT_FLOATS (NTHREADS * HID * 2)    // 32768 floats = 128 KB
#define SMEM_FLOATS (OFF_ACT + ACT_FLOATS)
#define SMEM_BYTES (SMEM_FLOATS * 4)       // ~202 KB

struct KParams {
    const float* in[30];
    float* out;
    int B;
};

__device__ __constant__ int kCnt[28] = {
    5, 5, 3, 3,
    448, 64, 4096, 64, 64, 1,
    448, 64, 4096, 64, 64, 1,
    384, 64, 4096, 64, 64, 1,
    320, 64, 4096, 64, 192, 3
};
__device__ __constant__ int kOff[28] = {
    OFF_IMEAN, OFF_ISTD, OFF_TMEAN, OFF_TSTD,
    OFF_SW1, OFF_SB1, OFF_SW2, OFF_SB2, OFF_SW3, OFF_SB3,
    OFF_AW1, OFF_AB1, OFF_AW2, OFF_AB2, OFF_AW3, OFF_AB3,
    OFF_FW1, OFF_FB1, OFF_FW2, OFF_FB2, OFF_FW3, OFF_FB3,
    OFF_RW1, OFF_RB1, OFF_RW2, OFF_RB2, OFF_RW3, OFF_RB3
};

// ---------------- packed f32x2 helpers ----------------
__device__ __forceinline__ u64 dup2(float a) {
    u64 r; asm("mov.b64 %0, {%1, %1};" : "=l"(r) : "f"(a)); return r;
}
__device__ __forceinline__ u64 ffma2(u64 a, u64 b, u64 c) {
    u64 d; asm("fma.rn.f32x2 %0, %1, %2, %3;" : "=l"(d) : "l"(a), "l"(b), "l"(c)); return d;
}
__device__ __forceinline__ float2 unpk2(u64 a) {
    float2 f; asm("mov.b64 {%0, %1}, %2;" : "=f"(f.x), "=f"(f.y) : "l"(a)); return f;
}

// accurate fast tanh: abs error ~1e-7, 2 MUFU (EX2 + RCP)
__device__ __forceinline__ float fast_tanhf(float x) {
    float ax = fabsf(x);
    float e  = __expf(2.0f * ax);
    float t  = 1.0f - __fdividef(2.0f, e + 1.0f);
    return (x < 0.0f) ? -t : t;
}

__device__ __forceinline__ float softplusf(float x) {
    float t = __expf(-fabsf(x));
    return fmaxf(x, 0.0f) + __logf(1.0f + t);
}

// Two rows through one MLP: DIN -> 64 (tanh) -> 64 (tanh) -> DOUT.
// Phase 1: layer-1 in two 32-output halves (acc1 = 64 regs), tanh(h1) -> SMEM.
// Phase 2: layer-2 in two 32-col chunks (acc2-chunk = 64 regs); each chunk
// reads full h from SMEM but each W2 column exactly once. acc1/acc2 never
// co-live -> ~130-160 regs total, leaving ptxas headroom to pipeline loads.
template <int DIN, int DOUT>
__device__ __forceinline__ void run_mlp2(
    const float* __restrict__ xa, const float* __restrict__ xb,
    const float* __restrict__ sm,
    float2* __restrict__ act,   // already offset by tid; stride NTHREADS
    int oW1, int ob1, int oW2, int ob2, int oW3, int ob3,
    float* __restrict__ outa, float* __restrict__ outb)
{
    // ---- phase 1: layer 1, DIN -> 64, two 32-output halves ----
#pragma unroll
    for (int half = 0; half < 2; half++) {
        u64 acc1a[16], acc1b[16];
        {
            const ulonglong2* b1 = (const ulonglong2*)(sm + ob1 + half * 32);
#pragma unroll
            for (int j = 0; j < 8; j++) {
                ulonglong2 b = b1[j];
                acc1a[2*j] = b.x; acc1a[2*j+1] = b.y;
                acc1b[2*j] = b.x; acc1b[2*j+1] = b.y;
            }
        }
#pragma unroll
        for (int i = 0; i < DIN; i++) {
            const ulonglong2* w = (const ulonglong2*)(sm + oW1 + i * HID + half * 32);
            u64 x2a = dup2(xa[i]);
            u64 x2b = dup2(xb[i]);
#pragma unroll
            for (int j = 0; j < 8; j++) {
                ulonglong2 wv = w[j];
                acc1a[2*j]   = ffma2(x2a, wv.x, acc1a[2*j]);
                acc1a[2*j+1] = ffma2(x2a, wv.y, acc1a[2*j+1]);
                acc1b[2*j]   = ffma2(x2b, wv.x, acc1b[2*j]);
                acc1b[2*j+1] = ffma2(x2b, wv.y, acc1b[2*j+1]);
            }
        }
        // tanh -> smem as float2(rowA, rowB), neuron-major (per-thread slots)
#pragma unroll
        for (int j = 0; j < 16; j++) {
            float2 va = unpk2(acc1a[j]);
            float2 vb = unpk2(acc1b[j]);
            act[(half * 32 + 2*j)     * NTHREADS] = make_float2(fast_tanhf(va.x), fast_tanhf(vb.x));
            act[(half * 32 + 2*j + 1) * NTHREADS] = make_float2(fast_tanhf(va.y), fast_tanhf(vb.y));
        }
    }

    // ---- phase 2: layer 2 in two 32-col chunks + streaming layer 3 ----
    float oa[DOUT], ob_[DOUT];
#pragma unroll
    for (int o = 0; o < DOUT; o++) { float b = sm[ob3 + o]; oa[o] = b; ob_[o] = b; }

#pragma unroll
    for (int chunk = 0; chunk < 2; chunk++) {
        u64 acc2a[16], acc2b[16];
        {
            const ulonglong2* b2 = (const ulonglong2*)(sm + ob2 + chunk * 32);
#pragma unroll
            for (int j = 0; j < 8; j++) {
                ulonglong2 b = b2[j];
                acc2a[2*j] = b.x; acc2a[2*j+1] = b.y;
                acc2b[2*j] = b.x; acc2b[2*j+1] = b.y;
            }
        }
#pragma unroll 4
        for (int k = 0; k < HID; k++) {
            float2 h = act[k * NTHREADS];   // per-thread LDS.64
            u64 h2a = dup2(h.x);
            u64 h2b = dup2(h.y);
            const ulonglong2* w = (const ulonglong2*)(sm + oW2 + k * HID + chunk * 32);
#pragma unroll
            for (int j = 0; j < 8; j++) {
                ulonglong2 wv = w[j];
                acc2a[2*j]   = ffma2(h2a, wv.x, acc2a[2*j]);
                acc2a[2*j+1] = ffma2(h2a, wv.y, acc2a[2*j+1]);
                acc2b[2*j]   = ffma2(h2b, wv.x, acc2b[2*j]);
                acc2b[2*j+1] = ffma2(h2b, wv.y, acc2b[2*j+1]);
            }
        }
        // tanh + layer-3 partial for cols [chunk*32, chunk*32+32)
#pragma unroll
        for (int j = 0; j < 16; j++) {
            float2 va = unpk2(acc2a[j]);
            float ta0 = fast_tanhf(va.x), ta1 = fast_tanhf(va.y);
            float2 vb = unpk2(acc2b[j]);
            float tb0 = fast_tanhf(vb.x), tb1 = fast_tanhf(vb.y);
            int base = chunk * 32 + 2*j;
#pragma unroll
            for (int o = 0; o < DOUT; o++) {
                float w0 = sm[oW3 + base * DOUT + o];
                float w1 = sm[oW3 + (base + 1) * DOUT + o];
                oa[o]  = fmaf(ta0, w0, fmaf(ta1, w1, oa[o]));
                ob_[o] = fmaf(tb0, w0, fmaf(tb1, w1, ob_[o]));
            }
        }
    }
#pragma unroll
    for (int o = 0; o < DOUT; o++) { outa[o] = oa[o]; outb[o] = ob_[o]; }
}

extern __shared__ float sm[];

__global__ void __launch_bounds__(NTHREADS, 1)
fused_mlp_kernel(KParams p)
{
    const int tid = threadIdx.x;

    // Stage all weights + norm params into SMEM once per CTA.
    for (int a = 0; a < 28; a++) {
        const float* src = p.in[a + 2];
        const int n = kCnt[a];
        const int o = kOff[a];
        for (int k = tid; k < n; k += NTHREADS) sm[o + k] = src[k];
    }
    __syncthreads();

    float2* act = (float2*)(sm + OFF_ACT) + tid;

    const float* xd0 = p.in[0];
    const float* utr = p.in[1];
    const int Btot = p.B;
    const int npairs = (Btot + 1) >> 1;
    const int stride = gridDim.x * NTHREADS;

    const float im0 = sm[OFF_IMEAN+0], im1 = sm[OFF_IMEAN+1], im2 = sm[OFF_IMEAN+2];
    const float im3 = sm[OFF_IMEAN+3], im4 = sm[OFF_IMEAN+4];
    const float is0 = sm[OFF_ISTD+0],  is1 = sm[OFF_ISTD+1],  is2 = sm[OFF_ISTD+2];
    const float is3 = sm[OFF_ISTD+3],  is4 = sm[OFF_ISTD+4];

    for (int pr = blockIdx.x * NTHREADS + tid; pr < npairs; pr += stride) {
        int ra = 2 * pr;
        int rb = 2 * pr + 1;
        bool hasb = (rb < Btot);
        int rbe = hasb ? rb : ra;

        float fa[5], fb[5]; // vx, vy, w, vel, delta per row
        {
            float a0 = xd0[ra*3+0], a1 = xd0[ra*3+1], a2 = xd0[ra*3+2];
            float a3 = utr[ra*2+0], a4 = utr[ra*2+1];
            fa[0] = __fdividef(a0 - im0, is0);
            fa[1] = __fdividef(a1 - im1, is1);
            fa[2] = __fdividef(a2 - im2, is2);
            fa[3] = __fdividef(a3 - im3, is3);
            fa[4] = __fdividef(a4 - im4, is4);
            float b0 = xd0[rbe*3+0], b1 = xd0[rbe*3+1], b2 = xd0[rbe*3+2];
            float b3 = utr[rbe*2+0], b4 = utr[rbe*2+1];
            fb[0] = __fdividef(b0 - im0, is0);
            fb[1] = __fdividef(b1 - im1, is1);
            fb[2] = __fdividef(b2 - im2, is2);
            fb[3] = __fdividef(b3 - im3, is3);
            fb[4] = __fdividef(b4 - im4, is4);
        }
        float vma = sqrtf(fmaf(fa[0], fa[0], fmaf(fa[1], fa[1], 1e-8f)));
        float vmb = sqrtf(fmaf(fb[0], fb[0], fmaf(fb[1], fb[1], 1e-8f)));
        float sga = (fa[0] > 0.0f) ? 1.0f : ((fa[0] < 0.0f) ? -1.0f : 0.0f);
        float sgb = (fb[0] > 0.0f) ? 1.0f : ((fb[0] < 0.0f) ? -1.0f : 0.0f);

        // steer MLP: [delta, vel, vx, vy, w, mag, sign]
        float sia[7] = {fa[4], fa[3], fa[0], fa[1], fa[2], vma, sga};
        float sib[7] = {fb[4], fb[3], fb[0], fb[1], fb[2], vmb, sgb};
        float soa, sob;
        run_mlp2<7,1>(sia, sib, sm, act, OFF_SW1, OFF_SB1, OFF_SW2, OFF_SB2, OFF_SW3, OFF_SB3, &soa, &sob);
        float dsa = 0.5f * fast_tanhf(soa);
        float dsb = 0.5f * fast_tanhf(sob);

        // acc MLP: [vel, delta, vx, mag, sign, vy, w]
        float aia[7] = {fa[3], fa[4], fa[0], vma, sga, fa[1], fa[2]};
        float aib[7] = {fb[3], fb[4], fb[0], vmb, sgb, fb[1], fb[2]};
        float aoa, aob;
        run_mlp2<7,1>(aia, aib, sm, act, OFF_AW1, OFF_AB1, OFF_AW2, OFF_AB2, OFF_AW3, OFF_AB3, &aoa, &aob);
        float daa = 0.5f * fast_tanhf(aoa);
        float dab = 0.5f * fast_tanhf(aob);

        float ue0a = fa[3] + daa, ue1a = fa[4] + dsa;
        float ue0b = fb[3] + dab, ue1b = fb[4] + dsb;

        // friction MLP: [vx, vy, w, ue0, ue1, DT]
        float fia[6] = {fa[0], fa[1], fa[2], ue0a, ue1a, 0.02f};
        float fib[6] = {fb[0], fb[1], fb[2], ue0b, ue1b, 0.02f};
        float foa, fob;
        run_mlp2<6,1>(fia, fib, sm, act, OFF_FW1, OFF_FB1, OFF_FW2, OFF_FB2, OFF_FW3, OFF_FB3, &foa, &fob);
        float fka = 1.0f + softplusf(foa);
        float fkb = 1.0f + softplusf(fob);

        // residual MLP: [vx, vy, w, ue0, ue1]
        float ria[5] = {fa[0], fa[1], fa[2], ue0a, ue1a};
        float rib[5] = {fb[0], fb[1], fb[2], ue0b, ue1b};
        float roa[3], rob[3];
        run_mlp2<5,3>(ria, rib, sm, act, OFF_RW1, OFF_RB1, OFF_RW2, OFF_RB2, OFF_RW3, OFF_RB3, roa, rob);

        float ts0 = sm[OFF_TSTD+0], ts1 = sm[OFF_TSTD+1], ts2 = sm[OFF_TSTD+2];
        float tm0 = sm[OFF_TMEAN+0], tm1 = sm[OFF_TMEAN+1], tm2 = sm[OFF_TMEAN+2];

        // outputs: [ut_eff_raw (B,2)] [friction_k (B,1)] [residual (B,3)]
        p.out[ra*2+0] = fmaf(ue0a, is3, im3);
        p.out[ra*2+1] = fmaf(ue1a, is4, im4);
        p.out[2*Btot + ra] = fka;
        p.out[3*Btot + ra*3 + 0] = fmaf(roa[0], ts0, tm0);
        p.out[3*Btot + ra*3 + 1] = fmaf(roa[1], ts1, tm1);
        p.out[3*Btot + ra*3 + 2] = fmaf(roa[2], ts2, tm2);
        if (hasb) {
            p.out[rb*2+0] = fmaf(ue0b, is3, im3);
            p.out[rb*2+1] = fmaf(ue1b, is4, im4);
            p.out[2*Btot + rb] = fkb;
            p.out[3*Btot + rb*3 + 0] = fmaf(rob[0], ts0, tm0);
            p.out[3*Btot + rb*3 + 1] = fmaf(rob[1], ts1, tm1);
            p.out[3*Btot + rb*3 + 2] = fmaf(rob[2], ts2, tm2);
        }
    }
}

extern "C" void kernel_launch(void* const* d_in, const int* in_sizes, int n_in,
                              void* d_out, int out_size)
{
    KParams p;
    for (int i = 0; i < 30; i++) p.in[i] = (const float*)d_in[i];
    p.out = (float*)d_out;
    p.B = in_sizes[0] / 3;

    cudaFuncSetAttribute(fused_mlp_kernel,
                         cudaFuncAttributeMaxDynamicSharedMemorySize, SMEM_BYTES);
    fused_mlp_kernel<<<GRID, NTHREADS, SMEM_BYTES>>>(p);
}

// round 9
// speedup vs baseline: 1.4979x; 1.2743x over previous
#include <cuda_runtime.h>
#include <math.h>

#define NTHREADS 256
#define HID 64
#define GRID 148   // 1 CTA per SM, persistent

typedef unsigned long long u64;

// ---------------- SMEM layout (float offsets) ----------------
#define OFF_SW1 0
#define OFF_SB1 448
#define OFF_SW2 512
#define OFF_SB2 4608
#define OFF_SW3 4672
#define OFF_SB3 4736
#define OFF_AW1 4740
#define OFF_AB1 5188
#define OFF_AW2 5252
#define OFF_AB2 9348
#define OFF_AW3 9412
#define OFF_AB3 9476
#define OFF_FW1 9480
#define OFF_FB1 9864
#define OFF_FW2 9928
#define OFF_FB2 14024
#define OFF_FW3 14088
#define OFF_FB3 14152
#define OFF_RW1 14156
#define OFF_RB1 14476
#define OFF_RW2 14540
#define OFF_RB2 18636
#define OFF_RW3 18700
#define OFF_RB3 18892
#define OFF_IMEAN 18896
#define OFF_ISTD  18904
#define OFF_TMEAN 18912
#define OFF_TSTD  18916
#define OFF_ACT   18920                    // float2 per (neuron, thread): rows a,b
#define ACT_FLOATS (NTHREADS * HID * 2)    // 32768 floats = 128 KB
#define SMEM_FLOATS (OFF_ACT + ACT_FLOATS)
#define SMEM_BYTES (SMEM_FLOATS * 4)       // ~202 KB

struct KParams {
    const float* in[30];
    float* out;
    int B;
};

__device__ __constant__ int kCnt[28] = {
    5, 5, 3, 3,
    448, 64, 4096, 64, 64, 1,
    448, 64, 4096, 64, 64, 1,
    384, 64, 4096, 64, 64, 1,
    320, 64, 4096, 64, 192, 3
};
__device__ __constant__ int kOff[28] = {
    OFF_IMEAN, OFF_ISTD, OFF_TMEAN, OFF_TSTD,
    OFF_SW1, OFF_SB1, OFF_SW2, OFF_SB2, OFF_SW3, OFF_SB3,
    OFF_AW1, OFF_AB1, OFF_AW2, OFF_AB2, OFF_AW3, OFF_AB3,
    OFF_FW1, OFF_FB1, OFF_FW2, OFF_FB2, OFF_FW3, OFF_FB3,
    OFF_RW1, OFF_RB1, OFF_RW2, OFF_RB2, OFF_RW3, OFF_RB3
};

// ---------------- packed f32x2 helpers ----------------
__device__ __forceinline__ u64 dup2(float a) {
    u64 r; asm("mov.b64 %0, {%1, %1};" : "=l"(r) : "f"(a)); return r;
}
__device__ __forceinline__ u64 ffma2(u64 a, u64 b, u64 c) {
    u64 d; asm("fma.rn.f32x2 %0, %1, %2, %3;" : "=l"(d) : "l"(a), "l"(b), "l"(c)); return d;
}
__device__ __forceinline__ float2 unpk2(u64 a) {
    float2 f; asm("mov.b64 {%0, %1}, %2;" : "=f"(f.x), "=f"(f.y) : "l"(a)); return f;
}

// HW tanh: 1 MUFU op, abs err ~5e-4 (used for hidden layers)
__device__ __forceinline__ float tanh_hw(float x) {
    float r; asm("tanh.approx.f32 %0, %1;" : "=f"(r) : "f"(x)); return r;
}

// accurate tanh for the two FINAL activations: abs err ~1e-7
__device__ __forceinline__ float tanh_exact(float x) {
    float ax = fabsf(x);
    float e  = __expf(2.0f * ax);
    float t  = 1.0f - __fdividef(2.0f, e + 1.0f);
    return (x < 0.0f) ? -t : t;
}

__device__ __forceinline__ float softplusf(float x) {
    float t = __expf(-fabsf(x));
    return fmaxf(x, 0.0f) + __logf(1.0f + t);
}

// Two rows through one MLP: DIN -> 64 (tanh) -> 64 (tanh) -> DOUT.
// Phase 1: layer-1 in two 32-output halves (acc1 = 64 regs), tanh(h1) -> SMEM.
// Phase 2: layer-2 in two 32-col chunks (acc2-chunk = 64 regs).
// Hidden tanh = single MUFU.TANH (no chains, no temps).
template <int DIN, int DOUT>
__device__ __forceinline__ void run_mlp2(
    const float* __restrict__ xa, const float* __restrict__ xb,
    const float* __restrict__ sm,
    float2* __restrict__ act,   // already offset by tid; stride NTHREADS
    int oW1, int ob1, int oW2, int ob2, int oW3, int ob3,
    float* __restrict__ outa, float* __restrict__ outb)
{
    // ---- phase 1: layer 1, DIN -> 64, two 32-output halves ----
#pragma unroll
    for (int half = 0; half < 2; half++) {
        u64 acc1a[16], acc1b[16];
        {
            const ulonglong2* b1 = (const ulonglong2*)(sm + ob1 + half * 32);
#pragma unroll
            for (int j = 0; j < 8; j++) {
                ulonglong2 b = b1[j];
                acc1a[2*j] = b.x; acc1a[2*j+1] = b.y;
                acc1b[2*j] = b.x; acc1b[2*j+1] = b.y;
            }
        }
#pragma unroll
        for (int i = 0; i < DIN; i++) {
            const ulonglong2* w = (const ulonglong2*)(sm + oW1 + i * HID + half * 32);
            u64 x2a = dup2(xa[i]);
            u64 x2b = dup2(xb[i]);
#pragma unroll
            for (int j = 0; j < 8; j++) {
                ulonglong2 wv = w[j];
                acc1a[2*j]   = ffma2(x2a, wv.x, acc1a[2*j]);
                acc1a[2*j+1] = ffma2(x2a, wv.y, acc1a[2*j+1]);
                acc1b[2*j]   = ffma2(x2b, wv.x, acc1b[2*j]);
                acc1b[2*j+1] = ffma2(x2b, wv.y, acc1b[2*j+1]);
            }
        }
        // tanh -> smem as float2(rowA, rowB), neuron-major (per-thread slots)
#pragma unroll
        for (int j = 0; j < 16; j++) {
            float2 va = unpk2(acc1a[j]);
            float2 vb = unpk2(acc1b[j]);
            act[(half * 32 + 2*j)     * NTHREADS] = make_float2(tanh_hw(va.x), tanh_hw(vb.x));
            act[(half * 32 + 2*j + 1) * NTHREADS] = make_float2(tanh_hw(va.y), tanh_hw(vb.y));
        }
    }

    // ---- phase 2: layer 2 in two 32-col chunks + streaming layer 3 ----
    float oa[DOUT], ob_[DOUT];
#pragma unroll
    for (int o = 0; o < DOUT; o++) { float b = sm[ob3 + o]; oa[o] = b; ob_[o] = b; }

#pragma unroll
    for (int chunk = 0; chunk < 2; chunk++) {
        u64 acc2a[16], acc2b[16];
        {
            const ulonglong2* b2 = (const ulonglong2*)(sm + ob2 + chunk * 32);
#pragma unroll
            for (int j = 0; j < 8; j++) {
                ulonglong2 b = b2[j];
                acc2a[2*j] = b.x; acc2a[2*j+1] = b.y;
                acc2b[2*j] = b.x; acc2b[2*j+1] = b.y;
            }
        }
#pragma unroll 4
        for (int k = 0; k < HID; k++) {
            float2 h = act[k * NTHREADS];   // per-thread LDS.64
            u64 h2a = dup2(h.x);
            u64 h2b = dup2(h.y);
            const ulonglong2* w = (const ulonglong2*)(sm + oW2 + k * HID + chunk * 32);
#pragma unroll
            for (int j = 0; j < 8; j++) {
                ulonglong2 wv = w[j];
                acc2a[2*j]   = ffma2(h2a, wv.x, acc2a[2*j]);
                acc2a[2*j+1] = ffma2(h2a, wv.y, acc2a[2*j+1]);
                acc2b[2*j]   = ffma2(h2b, wv.x, acc2b[2*j]);
                acc2b[2*j+1] = ffma2(h2b, wv.y, acc2b[2*j+1]);
            }
        }
        // tanh + layer-3 partial for cols [chunk*32, chunk*32+32)
#pragma unroll
        for (int j = 0; j < 16; j++) {
            float2 va = unpk2(acc2a[j]);
            float ta0 = tanh_hw(va.x), ta1 = tanh_hw(va.y);
            float2 vb = unpk2(acc2b[j]);
            float tb0 = tanh_hw(vb.x), tb1 = tanh_hw(vb.y);
            int base = chunk * 32 + 2*j;
#pragma unroll
            for (int o = 0; o < DOUT; o++) {
                float w0 = sm[oW3 + base * DOUT + o];
                float w1 = sm[oW3 + (base + 1) * DOUT + o];
                oa[o]  = fmaf(ta0, w0, fmaf(ta1, w1, oa[o]));
                ob_[o] = fmaf(tb0, w0, fmaf(tb1, w1, ob_[o]));
            }
        }
    }
#pragma unroll
    for (int o = 0; o < DOUT; o++) { outa[o] = oa[o]; outb[o] = ob_[o]; }
}

extern __shared__ float sm[];

__global__ void __launch_bounds__(NTHREADS, 1)
fused_mlp_kernel(KParams p)
{
    const int tid = threadIdx.x;

    // Stage all weights + norm params into SMEM once per CTA.
    for (int a = 0; a < 28; a++) {
        const float* src = p.in[a + 2];
        const int n = kCnt[a];
        const int o = kOff[a];
        for (int k = tid; k < n; k += NTHREADS) sm[o + k] = src[k];
    }
    __syncthreads();

    float2* act = (float2*)(sm + OFF_ACT) + tid;

    const float* xd0 = p.in[0];
    const float* utr = p.in[1];
    const int Btot = p.B;
    const int npairs = (Btot + 1) >> 1;
    const int stride = gridDim.x * NTHREADS;

    const float im0 = sm[OFF_IMEAN+0], im1 = sm[OFF_IMEAN+1], im2 = sm[OFF_IMEAN+2];
    const float im3 = sm[OFF_IMEAN+3], im4 = sm[OFF_IMEAN+4];
    const float is0 = sm[OFF_ISTD+0],  is1 = sm[OFF_ISTD+1],  is2 = sm[OFF_ISTD+2];
    const float is3 = sm[OFF_ISTD+3],  is4 = sm[OFF_ISTD+4];

    for (int pr = blockIdx.x * NTHREADS + tid; pr < npairs; pr += stride) {
        int ra = 2 * pr;
        int rb = 2 * pr + 1;
        bool hasb = (rb < Btot);
        int rbe = hasb ? rb : ra;

        float fa[5], fb[5]; // vx, vy, w, vel, delta per row
        {
            float a0 = xd0[ra*3+0], a1 = xd0[ra*3+1], a2 = xd0[ra*3+2];
            float a3 = utr[ra*2+0], a4 = utr[ra*2+1];
            fa[0] = __fdividef(a0 - im0, is0);
            fa[1] = __fdividef(a1 - im1, is1);
            fa[2] = __fdividef(a2 - im2, is2);
            fa[3] = __fdividef(a3 - im3, is3);
            fa[4] = __fdividef(a4 - im4, is4);
            float b0 = xd0[rbe*3+0], b1 = xd0[rbe*3+1], b2 = xd0[rbe*3+2];
            float b3 = utr[rbe*2+0], b4 = utr[rbe*2+1];
            fb[0] = __fdividef(b0 - im0, is0);
            fb[1] = __fdividef(b1 - im1, is1);
            fb[2] = __fdividef(b2 - im2, is2);
            fb[3] = __fdividef(b3 - im3, is3);
            fb[4] = __fdividef(b4 - im4, is4);
        }
        float vma = sqrtf(fmaf(fa[0], fa[0], fmaf(fa[1], fa[1], 1e-8f)));
        float vmb = sqrtf(fmaf(fb[0], fb[0], fmaf(fb[1], fb[1], 1e-8f)));
        float sga = (fa[0] > 0.0f) ? 1.0f : ((fa[0] < 0.0f) ? -1.0f : 0.0f);
        float sgb = (fb[0] > 0.0f) ? 1.0f : ((fb[0] < 0.0f) ? -1.0f : 0.0f);

        // steer MLP: [delta, vel, vx, vy, w, mag, sign]
        float sia[7] = {fa[4], fa[3], fa[0], fa[1], fa[2], vma, sga};
        float sib[7] = {fb[4], fb[3], fb[0], fb[1], fb[2], vmb, sgb};
        float soa, sob;
        run_mlp2<7,1>(sia, sib, sm, act, OFF_SW1, OFF_SB1, OFF_SW2, OFF_SB2, OFF_SW3, OFF_SB3, &soa, &sob);
        float dsa = 0.5f * tanh_exact(soa);
        float dsb = 0.5f * tanh_exact(sob);

        // acc MLP: [vel, delta, vx, mag, sign, vy, w]
        float aia[7] = {fa[3], fa[4], fa[0], vma, sga, fa[1], fa[2]};
        float aib[7] = {fb[3], fb[4], fb[0], vmb, sgb, fb[1], fb[2]};
        float aoa, aob;
        run_mlp2<7,1>(aia, aib, sm, act, OFF_AW1, OFF_AB1, OFF_AW2, OFF_AB2, OFF_AW3, OFF_AB3, &aoa, &aob);
        float daa = 0.5f * tanh_exact(aoa);
        float dab = 0.5f * tanh_exact(aob);

        float ue0a = fa[3] + daa, ue1a = fa[4] + dsa;
        float ue0b = fb[3] + dab, ue1b = fb[4] + dsb;

        // friction MLP: [vx, vy, w, ue0, ue1, DT]
        float fia[6] = {fa[0], fa[1], fa[2], ue0a, ue1a, 0.02f};
        float fib[6] = {fb[0], fb[1], fb[2], ue0b, ue1b, 0.02f};
        float foa, fob;
        run_mlp2<6,1>(fia, fib, sm, act, OFF_FW1, OFF_FB1, OFF_FW2, OFF_FB2, OFF_FW3, OFF_FB3, &foa, &fob);
        float fka = 1.0f + softplusf(foa);
        float fkb = 1.0f + softplusf(fob);

        // residual MLP: [vx, vy, w, ue0, ue1]
        float ria[5] = {fa[0], fa[1], fa[2], ue0a, ue1a};
        float rib[5] = {fb[0], fb[1], fb[2], ue0b, ue1b};
        float roa[3], rob[3];
        run_mlp2<5,3>(ria, rib, sm, act, OFF_RW1, OFF_RB1, OFF_RW2, OFF_RB2, OFF_RW3, OFF_RB3, roa, rob);

        float ts0 = sm[OFF_TSTD+0], ts1 = sm[OFF_TSTD+1], ts2 = sm[OFF_TSTD+2];
        float tm0 = sm[OFF_TMEAN+0], tm1 = sm[OFF_TMEAN+1], tm2 = sm[OFF_TMEAN+2];

        // outputs: [ut_eff_raw (B,2)] [friction_k (B,1)] [residual (B,3)]
        p.out[ra*2+0] = fmaf(ue0a, is3, im3);
        p.out[ra*2+1] = fmaf(ue1a, is4, im4);
        p.out[2*Btot + ra] = fka;
        p.out[3*Btot + ra*3 + 0] = fmaf(roa[0], ts0, tm0);
        p.out[3*Btot + ra*3 + 1] = fmaf(roa[1], ts1, tm1);
        p.out[3*Btot + ra*3 + 2] = fmaf(roa[2], ts2, tm2);
        if (hasb) {
            p.out[rb*2+0] = fmaf(ue0b, is3, im3);
            p.out[rb*2+1] = fmaf(ue1b, is4, im4);
            p.out[2*Btot + rb] = fkb;
            p.out[3*Btot + rb*3 + 0] = fmaf(rob[0], ts0, tm0);
            p.out[3*Btot + rb*3 + 1] = fmaf(rob[1], ts1, tm1);
            p.out[3*Btot + rb*3 + 2] = fmaf(rob[2], ts2, tm2);
        }
    }
}

extern "C" void kernel_launch(void* const* d_in, const int* in_sizes, int n_in,
                              void* d_out, int out_size)
{
    KParams p;
    for (int i = 0; i < 30; i++) p.in[i] = (const float*)d_in[i];
    p.out = (float*)d_out;
    p.B = in_sizes[0] / 3;

    cudaFuncSetAttribute(fused_mlp_kernel,
                         cudaFuncAttributeMaxDynamicSharedMemorySize, SMEM_BYTES);
    fused_mlp_kernel<<<GRID, NTHREADS, SMEM_BYTES>>>(p);
}

// round 10
// speedup vs baseline: 1.6071x; 1.0729x over previous
#include <cuda_runtime.h>
#include <cuda_fp16.h>
#include <math.h>

#define NTHREADS 256
#define HID 64
#define GRID 148   // 1 CTA per SM, persistent

typedef unsigned long long u64;
typedef unsigned int u32;

// ---------------- SMEM layout (float offsets) ----------------
#define OFF_SW1 0
#define OFF_SB1 448
#define OFF_SW2 512
#define OFF_SB2 4608
#define OFF_SW3 4672
#define OFF_SB3 4736
#define OFF_AW1 4740
#define OFF_AB1 5188
#define OFF_AW2 5252
#define OFF_AB2 9348
#define OFF_AW3 9412
#define OFF_AB3 9476
#define OFF_FW1 9480
#define OFF_FB1 9864
#define OFF_FW2 9928
#define OFF_FB2 14024
#define OFF_FW3 14088
#define OFF_FB3 14152
#define OFF_RW1 14156
#define OFF_RB1 14476
#define OFF_RW2 14540
#define OFF_RB2 18636
#define OFF_RW3 18700
#define OFF_RB3 18892
#define OFF_IMEAN 18896
#define OFF_ISTD  18904
#define OFF_TMEAN 18912
#define OFF_TSTD  18916
#define OFF_ACT   18920                    // u64 per (neuron, thread): 4 rows as fp16x4
#define ACT_U64   (NTHREADS * HID)         // 16384 u64 = 128 KB
#define SMEM_BYTES (OFF_ACT * 4 + ACT_U64 * 8)   // 206752 B

struct KParams {
    const float* in[30];
    float* out;
    int B;
};

__device__ __constant__ int kCnt[28] = {
    5, 5, 3, 3,
    448, 64, 4096, 64, 64, 1,
    448, 64, 4096, 64, 64, 1,
    384, 64, 4096, 64, 64, 1,
    320, 64, 4096, 64, 192, 3
};
__device__ __constant__ int kOff[28] = {
    OFF_IMEAN, OFF_ISTD, OFF_TMEAN, OFF_TSTD,
    OFF_SW1, OFF_SB1, OFF_SW2, OFF_SB2, OFF_SW3, OFF_SB3,
    OFF_AW1, OFF_AB1, OFF_AW2, OFF_AB2, OFF_AW3, OFF_AB3,
    OFF_FW1, OFF_FB1, OFF_FW2, OFF_FB2, OFF_FW3, OFF_FB3,
    OFF_RW1, OFF_RB1, OFF_RW2, OFF_RB2, OFF_RW3, OFF_RB3
};

// ---------------- packed helpers ----------------
__device__ __forceinline__ u64 dup2(float a) {
    u64 r; asm("mov.b64 %0, {%1, %1};" : "=l"(r) : "f"(a)); return r;
}
__device__ __forceinline__ u64 ffma2(u64 a, u64 b, u64 c) {
    u64 d; asm("fma.rn.f32x2 %0, %1, %2, %3;" : "=l"(d) : "l"(a), "l"(b), "l"(c)); return d;
}
__device__ __forceinline__ float2 unpk2(u64 a) {
    float2 f; asm("mov.b64 {%0, %1}, %2;" : "=f"(f.x), "=f"(f.y) : "l"(a)); return f;
}
// pack 4 f32 -> 4 fp16 in one u64 (first operand of cvt.f16x2 is HIGH half)
__device__ __forceinline__ u64 pack_h4(float a, float b, float c, float d) {
    u32 lo, hi;
    asm("cvt.rn.f16x2.f32 %0, %1, %2;" : "=r"(lo) : "f"(b), "f"(a));
    asm("cvt.rn.f16x2.f32 %0, %1, %2;" : "=r"(hi) : "f"(d), "f"(c));
    u64 r; asm("mov.b64 %0, {%1, %2};" : "=l"(r) : "r"(lo), "r"(hi));
    return r;
}
__device__ __forceinline__ float4 unpack_h4(u64 v) {
    u32 lo, hi;
    asm("mov.b64 {%0, %1}, %2;" : "=r"(lo), "=r"(hi) : "l"(v));
    __half2 h0 = *reinterpret_cast<__half2*>(&lo);
    __half2 h1 = *reinterpret_cast<__half2*>(&hi);
    float2 f0 = __half22float2(h0);
    float2 f1 = __half22float2(h1);
    return make_float4(f0.x, f0.y, f1.x, f1.y);
}

// HW tanh: 1 MUFU op (hidden layers)
__device__ __forceinline__ float tanh_hw(float x) {
    float r; asm("tanh.approx.f32 %0, %1;" : "=f"(r) : "f"(x)); return r;
}
// accurate tanh for the two FINAL activations
__device__ __forceinline__ float tanh_exact(float x) {
    float ax = fabsf(x);
    float e  = __expf(2.0f * ax);
    float t  = 1.0f - __fdividef(2.0f, e + 1.0f);
    return (x < 0.0f) ? -t : t;
}
__device__ __forceinline__ float softplusf(float x) {
    float t = __expf(-fabsf(x));
    return fmaxf(x, 0.0f) + __logf(1.0f + t);
}

// FOUR rows through one MLP: DIN -> 64 (tanh) -> 64 (tanh) -> DOUT.
// Phase 1: layer-1 in two 32-output halves (acc = 128 regs); tanh(h1) stored
// to SMEM as fp16x4 (one u64 per neuron for all 4 rows).
// Phase 2: layer-2 in two 32-col chunks (acc = 128 regs); h re-read via one
// LDS.64 + 4 cvt per k. Every weight LDS feeds 8 FFMA2 (4 rows).
template <int DIN, int DOUT>
__device__ __forceinline__ void run_mlp4(
    const float* __restrict__ x,      // [4*DIN], row-major
    const float* __restrict__ sm,
    u64* __restrict__ act,            // offset by tid; stride NTHREADS
    int oW1, int ob1, int oW2, int ob2, int oW3, int ob3,
    float* __restrict__ outm)         // [4*DOUT]
{
    // ---- phase 1: layer 1, two 32-output halves ----
#pragma unroll
    for (int half = 0; half < 2; half++) {
        u64 acc[4][16];
        {
            const ulonglong2* b1 = (const ulonglong2*)(sm + ob1 + half * 32);
#pragma unroll
            for (int j = 0; j < 8; j++) {
                ulonglong2 b = b1[j];
#pragma unroll
                for (int r = 0; r < 4; r++) { acc[r][2*j] = b.x; acc[r][2*j+1] = b.y; }
            }
        }
#pragma unroll
        for (int i = 0; i < DIN; i++) {
            const ulonglong2* w = (const ulonglong2*)(sm + oW1 + i * HID + half * 32);
            u64 xd[4];
#pragma unroll
            for (int r = 0; r < 4; r++) xd[r] = dup2(x[r * DIN + i]);
#pragma unroll
            for (int j = 0; j < 8; j++) {
                ulonglong2 wv = w[j];
#pragma unroll
                for (int r = 0; r < 4; r++) {
                    acc[r][2*j]   = ffma2(xd[r], wv.x, acc[r][2*j]);
                    acc[r][2*j+1] = ffma2(xd[r], wv.y, acc[r][2*j+1]);
                }
            }
        }
        // tanh -> fp16x4 -> smem
#pragma unroll
        for (int j = 0; j < 16; j++) {
            float2 v0 = unpk2(acc[0][j]);
            float2 v1 = unpk2(acc[1][j]);
            float2 v2 = unpk2(acc[2][j]);
            float2 v3 = unpk2(acc[3][j]);
            act[(half*32 + 2*j)   * NTHREADS] = pack_h4(tanh_hw(v0.x), tanh_hw(v1.x), tanh_hw(v2.x), tanh_hw(v3.x));
            act[(half*32 + 2*j+1) * NTHREADS] = pack_h4(tanh_hw(v0.y), tanh_hw(v1.y), tanh_hw(v2.y), tanh_hw(v3.y));
        }
    }

    // ---- phase 2: layer 2 in two 32-col chunks + streaming layer 3 ----
    float o[4][DOUT];
#pragma unroll
    for (int oo = 0; oo < DOUT; oo++) {
        float b = sm[ob3 + oo];
#pragma unroll
        for (int r = 0; r < 4; r++) o[r][oo] = b;
    }

#pragma unroll
    for (int chunk = 0; chunk < 2; chunk++) {
        u64 acc[4][16];
        {
            const ulonglong2* b2 = (const ulonglong2*)(sm + ob2 + chunk * 32);
#pragma unroll
            for (int j = 0; j < 8; j++) {
                ulonglong2 b = b2[j];
#pragma unroll
                for (int r = 0; r < 4; r++) { acc[r][2*j] = b.x; acc[r][2*j+1] = b.y; }
            }
        }
#pragma unroll 4
        for (int k = 0; k < HID; k++) {
            float4 h = unpack_h4(act[k * NTHREADS]);
            u64 d0 = dup2(h.x), d1 = dup2(h.y), d2 = dup2(h.z), d3 = dup2(h.w);
            const ulonglong2* w = (const ulonglong2*)(sm + oW2 + k * HID + chunk * 32);
#pragma unroll
            for (int j = 0; j < 8; j++) {
                ulonglong2 wv = w[j];
                acc[0][2*j]   = ffma2(d0, wv.x, acc[0][2*j]);
                acc[0][2*j+1] = ffma2(d0, wv.y, acc[0][2*j+1]);
                acc[1][2*j]   = ffma2(d1, wv.x, acc[1][2*j]);
                acc[1][2*j+1] = ffma2(d1, wv.y, acc[1][2*j+1]);
                acc[2][2*j]   = ffma2(d2, wv.x, acc[2][2*j]);
                acc[2][2*j+1] = ffma2(d2, wv.y, acc[2][2*j+1]);
                acc[3][2*j]   = ffma2(d3, wv.x, acc[3][2*j]);
                acc[3][2*j+1] = ffma2(d3, wv.y, acc[3][2*j+1]);
            }
        }
        // tanh + layer-3 partial for cols [chunk*32, chunk*32+32)
#pragma unroll
        for (int j = 0; j < 16; j++) {
            int base = chunk * 32 + 2*j;
#pragma unroll
            for (int r = 0; r < 4; r++) {
                float2 v = unpk2(acc[r][j]);
                float t0 = tanh_hw(v.x), t1 = tanh_hw(v.y);
#pragma unroll
                for (int oo = 0; oo < DOUT; oo++) {
                    float w0 = sm[oW3 + base * DOUT + oo];
                    float w1 = sm[oW3 + (base + 1) * DOUT + oo];
                    o[r][oo] = fmaf(t0, w0, fmaf(t1, w1, o[r][oo]));
                }
            }
        }
    }
#pragma unroll
    for (int r = 0; r < 4; r++)
#pragma unroll
        for (int oo = 0; oo < DOUT; oo++) outm[r * DOUT + oo] = o[r][oo];
}

extern __shared__ float sm[];

__global__ void __launch_bounds__(NTHREADS, 1)
fused_mlp_kernel(KParams p)
{
    const int tid = threadIdx.x;

    // Stage all weights + norm params into SMEM once per CTA.
    for (int a = 0; a < 28; a++) {
        const float* src = p.in[a + 2];
        const int n = kCnt[a];
        const int o = kOff[a];
        for (int k = tid; k < n; k += NTHREADS) sm[o + k] = src[k];
    }
    __syncthreads();

    u64* act = (u64*)(sm + OFF_ACT) + tid;

    const float* xd0 = p.in[0];
    const float* utr = p.in[1];
    const int Btot = p.B;
    const int nquads = (Btot + 3) >> 2;
    const int stride = gridDim.x * NTHREADS;

    const float im0 = sm[OFF_IMEAN+0], im1 = sm[OFF_IMEAN+1], im2 = sm[OFF_IMEAN+2];
    const float im3 = sm[OFF_IMEAN+3], im4 = sm[OFF_IMEAN+4];
    const float is0 = sm[OFF_ISTD+0],  is1 = sm[OFF_ISTD+1],  is2 = sm[OFF_ISTD+2];
    const float is3 = sm[OFF_ISTD+3],  is4 = sm[OFF_ISTD+4];

    for (int q = blockIdx.x * NTHREADS + tid; q < nquads; q += stride) {
        const int r0 = 4 * q;
        float f[4][5];   // vx, vy, w, vel, delta per row
        if (r0 + 3 < Btot) {
            const float4* x4 = (const float4*)(xd0 + (size_t)r0 * 3);
            float4 A = x4[0], Bv = x4[1], C = x4[2];
            const float4* u4 = (const float4*)(utr + (size_t)r0 * 2);
            float4 U = u4[0], V = u4[1];
            f[0][0]=A.x;  f[0][1]=A.y;  f[0][2]=A.z;  f[0][3]=U.x; f[0][4]=U.y;
            f[1][0]=A.w;  f[1][1]=Bv.x; f[1][2]=Bv.y; f[1][3]=U.z; f[1][4]=U.w;
            f[2][0]=Bv.z; f[2][1]=Bv.w; f[2][2]=C.x;  f[2][3]=V.x; f[2][4]=V.y;
            f[3][0]=C.y;  f[3][1]=C.z;  f[3][2]=C.w;  f[3][3]=V.z; f[3][4]=V.w;
        } else {
#pragma unroll
            for (int r = 0; r < 4; r++) {
                int rr = min(r0 + r, Btot - 1);
                f[r][0] = xd0[rr*3+0]; f[r][1] = xd0[rr*3+1]; f[r][2] = xd0[rr*3+2];
                f[r][3] = utr[rr*2+0]; f[r][4] = utr[rr*2+1];
            }
        }
        float vm[4], sg[4];
#pragma unroll
        for (int r = 0; r < 4; r++) {
            f[r][0] = __fdividef(f[r][0] - im0, is0);
            f[r][1] = __fdividef(f[r][1] - im1, is1);
            f[r][2] = __fdividef(f[r][2] - im2, is2);
            f[r][3] = __fdividef(f[r][3] - im3, is3);
            f[r][4] = __fdividef(f[r][4] - im4, is4);
            vm[r] = sqrtf(fmaf(f[r][0], f[r][0], fmaf(f[r][1], f[r][1], 1e-8f)));
            sg[r] = (f[r][0] > 0.0f) ? 1.0f : ((f[r][0] < 0.0f) ? -1.0f : 0.0f);
        }

        // steer MLP: [delta, vel, vx, vy, w, mag, sign]
        float si[28], so[4];
#pragma unroll
        for (int r = 0; r < 4; r++) {
            si[r*7+0]=f[r][4]; si[r*7+1]=f[r][3]; si[r*7+2]=f[r][0];
            si[r*7+3]=f[r][1]; si[r*7+4]=f[r][2]; si[r*7+5]=vm[r]; si[r*7+6]=sg[r];
        }
        run_mlp4<7,1>(si, sm, act, OFF_SW1, OFF_SB1, OFF_SW2, OFF_SB2, OFF_SW3, OFF_SB3, so);

        // acc MLP: [vel, delta, vx, mag, sign, vy, w]
        float ai[28], ao[4];
#pragma unroll
        for (int r = 0; r < 4; r++) {
            ai[r*7+0]=f[r][3]; ai[r*7+1]=f[r][4]; ai[r*7+2]=f[r][0];
            ai[r*7+3]=vm[r];   ai[r*7+4]=sg[r];   ai[r*7+5]=f[r][1]; ai[r*7+6]=f[r][2];
        }
        run_mlp4<7,1>(ai, sm, act, OFF_AW1, OFF_AB1, OFF_AW2, OFF_AB2, OFF_AW3, OFF_AB3, ao);

        float ue0[4], ue1[4];
#pragma unroll
        for (int r = 0; r < 4; r++) {
            ue0[r] = f[r][3] + 0.5f * tanh_exact(ao[r]);
            ue1[r] = f[r][4] + 0.5f * tanh_exact(so[r]);
        }

        // friction MLP: [vx, vy, w, ue0, ue1, DT]
        float fi[24], fo[4];
#pragma unroll
        for (int r = 0; r < 4; r++) {
            fi[r*6+0]=f[r][0]; fi[r*6+1]=f[r][1]; fi[r*6+2]=f[r][2];
            fi[r*6+3]=ue0[r];  fi[r*6+4]=ue1[r];  fi[r*6+5]=0.02f;
        }
        run_mlp4<6,1>(fi, sm, act, OFF_FW1, OFF_FB1, OFF_FW2, OFF_FB2, OFF_FW3, OFF_FB3, fo);

        // residual MLP: [vx, vy, w, ue0, ue1]
        float ri[20], ro[12];
#pragma unroll
        for (int r = 0; r < 4; r++) {
            ri[r*5+0]=f[r][0]; ri[r*5+1]=f[r][1]; ri[r*5+2]=f[r][2];
            ri[r*5+3]=ue0[r];  ri[r*5+4]=ue1[r];
        }
        run_mlp4<5,3>(ri, sm, act, OFF_RW1, OFF_RB1, OFF_RW2, OFF_RB2, OFF_RW3, OFF_RB3, ro);

        const float ts0 = sm[OFF_TSTD+0], ts1 = sm[OFF_TSTD+1], ts2 = sm[OFF_TSTD+2];
        const float tm0 = sm[OFF_TMEAN+0], tm1 = sm[OFF_TMEAN+1], tm2 = sm[OFF_TMEAN+2];

        // outputs: [ut_eff_raw (B,2)] [friction_k (B,1)] [residual (B,3)]
#pragma unroll
        for (int r = 0; r < 4; r++) {
            int row = r0 + r;
            if (row < Btot) {
                p.out[row*2+0] = fmaf(ue0[r], is3, im3);
                p.out[row*2+1] = fmaf(ue1[r], is4, im4);
                p.out[2*Btot + row] = 1.0f + softplusf(fo[r]);
                p.out[3*Btot + row*3 + 0] = fmaf(ro[r*3+0], ts0, tm0);
                p.out[3*Btot + row*3 + 1] = fmaf(ro[r*3+1], ts1, tm1);
                p.out[3*Btot + row*3 + 2] = fmaf(ro[r*3+2], ts2, tm2);
            }
        }
    }
}

extern "C" void kernel_launch(void* const* d_in, const int* in_sizes, int n_in,
                              void* d_out, int out_size)
{
    KParams p;
    for (int i = 0; i < 30; i++) p.in[i] = (const float*)d_in[i];
    p.out = (float*)d_out;
    p.B = in_sizes[0] / 3;

    cudaFuncSetAttribute(fused_mlp_kernel,
                         cudaFuncAttributeMaxDynamicSharedMemorySize, SMEM_BYTES);
    fused_mlp_kernel<<<GRID, NTHREADS, SMEM_BYTES>>>(p);
}